// round 5
// baseline (speedup 1.0000x reference)
#include <cuda_runtime.h>
#include <cuda_bf16.h>
#include <cstdint>

#define Bb 64
#define Nn 1024
#define Cc 768
#define NHh 12
#define KDd 64
#define MROWS (Bb * Nn)

// ---------------- scratch ---------------------------------------------------
__device__ float g_q[Bb * NHh * Nn];
__device__ float g_w[Bb * NHh * Nn];
__device__ float g_sig[Bb * NHh];
__device__ float g_tp[Bb * 8 * NHh * Cc];
__device__ float g_cv[Bb * Cc];
__device__ __align__(16) __nv_bfloat16 g_xb[(size_t)MROWS * Cc];
__device__ __align__(16) __nv_bfloat16 g_vb[(size_t)MROWS * Cc];
__device__ __align__(16) __nv_bfloat16 g_wvb[Cc * Cc];
__device__ __align__(16) __nv_bfloat16 g_wob[Cc * Cc];

__device__ __forceinline__ uint32_t f2bf2(float lo, float hi) {
    uint32_t r;
    asm("cvt.rn.bf16x2.f32 %0, %1, %2;" : "=r"(r) : "f"(hi), "f"(lo));
    return r;
}
__device__ __forceinline__ uint32_t smem_u32(const void* p) {
    uint32_t a;
    asm("{ .reg .u64 t; cvta.to.shared.u64 t, %1; cvt.u32.u64 %0, t; }" : "=r"(a) : "l"(p));
    return a;
}
#define CP_COMMIT() asm volatile("cp.async.commit_group;" ::: "memory")
#define CP_WAIT2() asm volatile("cp.async.wait_group 2;" ::: "memory")

__device__ __forceinline__ void ldsm4(uint32_t& r0, uint32_t& r1, uint32_t& r2,
                                      uint32_t& r3, uint32_t a) {
    asm volatile("ldmatrix.sync.aligned.m8n8.x4.shared.b16 {%0,%1,%2,%3}, [%4];"
                 : "=r"(r0), "=r"(r1), "=r"(r2), "=r"(r3) : "r"(a));
}
__device__ __forceinline__ void mma_bf16(float c[4], const uint32_t a[4],
                                         const uint32_t b0, const uint32_t b1) {
    asm volatile(
        "mma.sync.aligned.m16n8k16.row.col.f32.bf16.bf16.f32 "
        "{%0,%1,%2,%3}, {%4,%5,%6,%7}, {%8,%9}, {%0,%1,%2,%3};"
        : "+f"(c[0]), "+f"(c[1]), "+f"(c[2]), "+f"(c[3])
        : "r"(a[0]), "r"(a[1]), "r"(a[2]), "r"(a[3]), "r"(b0), "r"(b1));
}

// ---------------- K0: weight conversion ------------------------------------
__global__ void __launch_bounds__(256) k0_wconv(const float* __restrict__ wqkv,
                                                const float* __restrict__ wout) {
    int o = blockIdx.x;
    int h = o >> 6, d = o & 63;
    const float2* s1 = (const float2*)(wqkv + (size_t)(h * 129 + 65 + d) * Cc);
    const float2* s2 = (const float2*)(wout + (size_t)o * Cc);
    uint32_t* d1 = (uint32_t*)g_wvb + o * (Cc / 2);
    uint32_t* d2 = (uint32_t*)g_wob + o * (Cc / 2);
    for (int i = threadIdx.x; i < Cc / 2; i += 256) {
        float2 a = s1[i]; d1[i] = f2bf2(a.x, a.y);
        float2 b = s2[i]; d2[i] = f2bf2(b.x, b.y);
    }
}

// ---------------- K1: q projection + x->bf16 --------------------------------
__global__ void __launch_bounds__(256) k1_qproj(const float* __restrict__ x,
                                                const float* __restrict__ wqkv,
                                                const float* __restrict__ bqkv) {
    __shared__ float sW[NHh][Cc];
    __shared__ float sB[NHh];
    int tid = threadIdx.x;
    for (int i = tid; i < NHh * Cc; i += 256) {
        int h = i / Cc, c = i % Cc;
        sW[h][c] = wqkv[(h * 129) * Cc + c];
    }
    if (tid < NHh) sB[tid] = bqkv[tid * 129];
    __syncthreads();

    int warp = tid >> 5, lane = tid & 31;
    int row0 = blockIdx.x * 128;
    for (int r = row0 + warp; r < row0 + 128; r += 8) {
        const float2* xr = (const float2*)(x + (size_t)r * Cc);
        uint32_t* xb = (uint32_t*)g_xb + (size_t)r * (Cc / 2);
        float acc[NHh];
#pragma unroll
        for (int h = 0; h < NHh; h++) acc[h] = 0.f;
#pragma unroll
        for (int i = 0; i < 12; i++) {
            int cp = lane + 32 * i;
            float2 xv = xr[cp];
            xb[cp] = f2bf2(xv.x, xv.y);
            int c = cp * 2;
#pragma unroll
            for (int h = 0; h < NHh; h++)
                acc[h] += xv.x * sW[h][c] + xv.y * sW[h][c + 1];
        }
#pragma unroll
        for (int h = 0; h < NHh; h++) {
#pragma unroll
            for (int off = 16; off; off >>= 1)
                acc[h] += __shfl_xor_sync(0xffffffffu, acc[h], off);
        }
        if (lane == 0) {
            int b = r >> 10, n = r & 1023;
#pragma unroll
            for (int h = 0; h < NHh; h++)
                g_q[((size_t)b * NHh + h) * Nn + n] = acc[h] + sB[h];
        }
    }
}

// ---------------- K2: softmax + *w_cv + sigma -------------------------------
__global__ void __launch_bounds__(256) k2_softmax(const float* __restrict__ wcv) {
    int bh = blockIdx.x;
    int tid = threadIdx.x;
    const float* q = g_q + (size_t)bh * Nn;
    __shared__ float red[256];

    float v0[4];
    float m = -1e30f;
#pragma unroll
    for (int i = 0; i < 4; i++) { v0[i] = q[tid + 256 * i]; m = fmaxf(m, v0[i]); }
    red[tid] = m; __syncthreads();
    for (int s = 128; s; s >>= 1) { if (tid < s) red[tid] = fmaxf(red[tid], red[tid + s]); __syncthreads(); }
    m = red[0]; __syncthreads();

    float e[4]; float sum = 0.f;
#pragma unroll
    for (int i = 0; i < 4; i++) { e[i] = expf(v0[i] - m); sum += e[i]; }
    red[tid] = sum; __syncthreads();
    for (int s = 128; s; s >>= 1) { if (tid < s) red[tid] += red[tid + s]; __syncthreads(); }
    float inv = 1.f / red[0]; __syncthreads();

    float wsum = 0.f;
#pragma unroll
    for (int i = 0; i < 4; i++) {
        int n = tid + 256 * i;
        float wv = e[i] * inv * wcv[n];
        g_w[(size_t)bh * Nn + n] = wv;
        wsum += wv;
    }
    red[tid] = wsum; __syncthreads();
    for (int s = 128; s; s >>= 1) { if (tid < s) red[tid] += red[tid + s]; __syncthreads(); }
    if (tid == 0) g_sig[bh] = red[0];
}

// ---------------- K3: t partials over 8 n-chunks ----------------------------
__global__ void __launch_bounds__(128) k3_t() {
    int b = blockIdx.y;
    int ch = blockIdx.z;
    int cp = blockIdx.x * 128 + threadIdx.x;
    __shared__ float sw[NHh * 128];
    for (int h = 0; h < NHh; h++)
        sw[h * 128 + threadIdx.x] = g_w[((size_t)b * NHh + h) * Nn + ch * 128 + threadIdx.x];
    __syncthreads();

    float acc0[NHh], acc1[NHh];
#pragma unroll
    for (int h = 0; h < NHh; h++) { acc0[h] = 0.f; acc1[h] = 0.f; }
    const uint32_t* xb = (const uint32_t*)g_xb + ((size_t)b * Nn + ch * 128) * (Cc / 2) + cp;
#pragma unroll 4
    for (int n = 0; n < 128; n++) {
        uint32_t u = xb[(size_t)n * (Cc / 2)];
        float lo = __uint_as_float(u << 16);
        float hi = __uint_as_float(u & 0xffff0000u);
#pragma unroll
        for (int h = 0; h < NHh; h++) {
            float wv = sw[h * 128 + n];
            acc0[h] += lo * wv;
            acc1[h] += hi * wv;
        }
    }
    float* tp = g_tp + ((size_t)(b * 8 + ch) * NHh) * Cc;
#pragma unroll
    for (int h = 0; h < NHh; h++) {
        tp[h * Cc + 2 * cp] = acc0[h];
        tp[h * Cc + 2 * cp + 1] = acc1[h];
    }
}

// ---------------- K4: cv ----------------------------------------------------
__global__ void __launch_bounds__(256) k4_cv(const float* __restrict__ wqkv,
                                             const float* __restrict__ bqkv) {
    int b = blockIdx.x;
    __shared__ float st[NHh * Cc];
    for (int i = threadIdx.x; i < NHh * Cc; i += 256) {
        float s = 0.f;
#pragma unroll
        for (int ch = 0; ch < 8; ch++)
            s += g_tp[((size_t)(b * 8 + ch) * NHh) * Cc + i];
        st[i] = s;
    }
    __syncthreads();

    int tid = threadIdx.x;
    int i0 = tid, i1 = tid + 256, i2 = tid + 512;
    int h0 = i0 >> 6, d0 = i0 & 63;
    int h1 = i1 >> 6, d1 = i1 & 63;
    int h2 = i2 >> 6, d2 = i2 & 63;
    const float4* w0 = (const float4*)(wqkv + (size_t)(h0 * 129 + 1 + d0) * Cc);
    const float4* w1 = (const float4*)(wqkv + (size_t)(h1 * 129 + 1 + d1) * Cc);
    const float4* w2 = (const float4*)(wqkv + (size_t)(h2 * 129 + 1 + d2) * Cc);
    const float4* t0 = (const float4*)(st + h0 * Cc);
    const float4* t1 = (const float4*)(st + h1 * Cc);
    const float4* t2 = (const float4*)(st + h2 * Cc);
    float a0 = 0.f, a1 = 0.f, a2 = 0.f;
#pragma unroll 4
    for (int i = 0; i < Cc / 4; i++) {
        float4 wa = w0[i], ta = t0[i];
        a0 += wa.x * ta.x + wa.y * ta.y + wa.z * ta.z + wa.w * ta.w;
        float4 wb = w1[i], tb = t1[i];
        a1 += wb.x * tb.x + wb.y * tb.y + wb.z * tb.z + wb.w * tb.w;
        float4 wc = w2[i], tc = t2[i];
        a2 += wc.x * tc.x + wc.y * tc.y + wc.z * tc.z + wc.w * tc.w;
    }
    g_cv[b * Cc + i0] = a0 + bqkv[h0 * 129 + 1 + d0] * g_sig[b * NHh + h0];
    g_cv[b * Cc + i1] = a1 + bqkv[h1 * 129 + 1 + d1] * g_sig[b * NHh + h1];
    g_cv[b * Cc + i2] = a2 + bqkv[h2 * 129 + 1 + d2] * g_sig[b * NHh + h2];
}

// ---------------- K5: bf16 HMMA GEMM, 128x128x64, slim addressing ----------
// MODE 0: A=g_xb, B=g_wvb, epilogue relu(v+bv)*cv -> g_vb (bf16)
// MODE 1: A=g_vb, B=g_wob, epilogue +b_out        -> out  (fp32)
#define K5_STAGES 3
#define K5_STAGE_BYTES 32768
#define K5_SMEM (K5_STAGES * K5_STAGE_BYTES)

template <int MODE>
__global__ void __launch_bounds__(256, 2) k5_gemm(const float* __restrict__ bias,
                                                  float* __restrict__ outg) {
    extern __shared__ char smem[];
    const uint32_t tb = smem_u32(smem);

    const int tid = threadIdx.x;
    const int warp = tid >> 5, lane = tid & 31;
    const int wm = warp >> 2, wn = warp & 3;
    const int gid = lane >> 2, tg = lane & 3;
    const int seg = lane >> 3, l7 = lane & 7;
    const int arow0 = blockIdx.y * 128;
    const int brow0 = blockIdx.x * 128;

    const __nv_bfloat16* Ab = (MODE == 0) ? g_xb : g_vb;
    const __nv_bfloat16* Bm = (MODE == 0) ? g_wvb : g_wob;

    // ---- slim load addressing: one pointer per tile, literal slot offsets --
    // slot i (i=0..3): row = (tid>>3) + 32*i  -> smem +4096*i, global +49152*i
    const char* gA = (const char*)Ab + ((size_t)(arow0 + (tid >> 3)) * 96 + (tid & 7)) * 16;
    const char* gB = (const char*)Bm + ((size_t)(brow0 + (tid >> 3)) * 96 + (tid & 7)) * 16;
    const uint32_t swo0 = (uint32_t)((tid >> 3) * 128 + (((tid & 7) ^ ((tid >> 3) & 7)) * 16));

    // ---- slim ldmatrix addressing ----
    // A fragment rows: wm*64 + mi*16 + (seg&1)*8 + l7 ; XOR term mi-invariant
    // B fragment rows: wn*32 + n2*16 + (seg>>1)*8 + l7
    const uint32_t aRowOff = (uint32_t)((wm * 64 + (seg & 1) * 8 + l7) * 128);
    const uint32_t bRowOff = (uint32_t)((wn * 32 + (seg >> 1) * 8 + l7) * 128);
    const uint32_t kselA = (uint32_t)(seg >> 1);
    const uint32_t kselB = (uint32_t)(seg & 1);

    float acc[4][4][4];
#pragma unroll
    for (int mi = 0; mi < 4; mi++)
#pragma unroll
        for (int ni = 0; ni < 4; ni++)
#pragma unroll
            for (int rg = 0; rg < 4; rg++) acc[mi][ni][rg] = 0.f;

#define K5_LOAD(kc, s)                                                          \
    do {                                                                        \
        uint32_t _aT = tb + (s) * K5_STAGE_BYTES + swo0;                        \
        uint32_t _bT = _aT + 16384;                                             \
        const char* _ga = gA + (kc) * 128;                                      \
        const char* _gb = gB + (kc) * 128;                                      \
        asm volatile(                                                           \
            "cp.async.cg.shared.global [%0], [%2], 16;\n\t"                     \
            "cp.async.cg.shared.global [%0+4096], [%2+49152], 16;\n\t"          \
            "cp.async.cg.shared.global [%0+8192], [%2+98304], 16;\n\t"          \
            "cp.async.cg.shared.global [%0+12288], [%2+147456], 16;\n\t"        \
            "cp.async.cg.shared.global [%1], [%3], 16;\n\t"                     \
            "cp.async.cg.shared.global [%1+4096], [%3+49152], 16;\n\t"          \
            "cp.async.cg.shared.global [%1+8192], [%3+98304], 16;\n\t"          \
            "cp.async.cg.shared.global [%1+12288], [%3+147456], 16;\n\t"        \
            :: "r"(_aT), "r"(_bT), "l"(_ga), "l"(_gb));                         \
    } while (0)

    K5_LOAD(0, 0); CP_COMMIT();
    K5_LOAD(1, 1); CP_COMMIT();

#pragma unroll 1
    for (int kc = 0; kc < 12; kc++) {
        if (kc + 2 < 12) K5_LOAD(kc + 2, (kc + 2) % K5_STAGES);
        CP_COMMIT();
        CP_WAIT2();
        __syncthreads();

        const uint32_t stBase = tb + (kc % K5_STAGES) * K5_STAGE_BYTES;
        const uint32_t aT = stBase + aRowOff;
        const uint32_t bT = stBase + 16384 + bRowOff;

#pragma unroll
        for (int ks = 0; ks < 4; ks++) {
            const uint32_t xa = (((uint32_t)(ks * 2) + kselA) ^ (uint32_t)l7) * 16u;
            const uint32_t xb = (((uint32_t)(ks * 2) + kselB) ^ (uint32_t)l7) * 16u;
            uint32_t af[4][4];
            uint32_t bf[2][4];
            const uint32_t a0 = aT + xa;
            ldsm4(af[0][0], af[0][1], af[0][2], af[0][3], a0);
            ldsm4(af[1][0], af[1][1], af[1][2], af[1][3], a0 + 2048);
            ldsm4(af[2][0], af[2][1], af[2][2], af[2][3], a0 + 4096);
            ldsm4(af[3][0], af[3][1], af[3][2], af[3][3], a0 + 6144);
            const uint32_t b0 = bT + xb;
            ldsm4(bf[0][0], bf[0][1], bf[0][2], bf[0][3], b0);
            ldsm4(bf[1][0], bf[1][1], bf[1][2], bf[1][3], b0 + 2048);
#pragma unroll
            for (int mi = 0; mi < 4; mi++) {
#pragma unroll
                for (int n2 = 0; n2 < 2; n2++) {
                    mma_bf16(acc[mi][2 * n2], af[mi], bf[n2][0], bf[n2][1]);
                    mma_bf16(acc[mi][2 * n2 + 1], af[mi], bf[n2][2], bf[n2][3]);
                }
            }
        }
        __syncthreads();
    }

    // epilogue
#pragma unroll
    for (int mi = 0; mi < 4; mi++) {
        int row = arow0 + wm * 64 + mi * 16 + gid;
#pragma unroll
        for (int ni = 0; ni < 4; ni++) {
            int col = brow0 + wn * 32 + ni * 8 + tg * 2;
            if (MODE == 0) {
                int hb = (col >> 6) * 129 + 65 + (col & 63);
                float bv0 = bias[hb], bv1 = bias[hb + 1];
                int b = row >> 10;
                float cv0 = g_cv[b * Cc + col], cv1 = g_cv[b * Cc + col + 1];
                float v00 = fmaxf(acc[mi][ni][0] + bv0, 0.f) * cv0;
                float v01 = fmaxf(acc[mi][ni][1] + bv1, 0.f) * cv1;
                float v10 = fmaxf(acc[mi][ni][2] + bv0, 0.f) * cv0;
                float v11 = fmaxf(acc[mi][ni][3] + bv1, 0.f) * cv1;
                uint32_t* dst = (uint32_t*)g_vb;
                dst[(size_t)row * (Cc / 2) + col / 2] = f2bf2(v00, v01);
                dst[(size_t)(row + 8) * (Cc / 2) + col / 2] = f2bf2(v10, v11);
            } else {
                float b0 = bias[col], b1 = bias[col + 1];
                *(float2*)(outg + (size_t)row * Cc + col) =
                    make_float2(acc[mi][ni][0] + b0, acc[mi][ni][1] + b1);
                *(float2*)(outg + (size_t)(row + 8) * Cc + col) =
                    make_float2(acc[mi][ni][2] + b0, acc[mi][ni][3] + b1);
            }
        }
    }
}

// ---------------- launch ----------------------------------------------------
extern "C" void kernel_launch(void* const* d_in, const int* in_sizes, int n_in,
                              void* d_out, int out_size) {
    const float* x = (const float*)d_in[0];
    const float* wqkv = (const float*)d_in[1];
    const float* bqkv = (const float*)d_in[2];
    const float* wcv = (const float*)d_in[3];
    const float* wout = (const float*)d_in[4];
    const float* bout = (const float*)d_in[5];
    float* out = (float*)d_out;

    cudaFuncSetAttribute(k5_gemm<0>, cudaFuncAttributeMaxDynamicSharedMemorySize, K5_SMEM);
    cudaFuncSetAttribute(k5_gemm<1>, cudaFuncAttributeMaxDynamicSharedMemorySize, K5_SMEM);

    k0_wconv<<<Cc, 256>>>(wqkv, wout);
    k1_qproj<<<512, 256>>>(x, wqkv, bqkv);
    k2_softmax<<<Bb * NHh, 256>>>(wcv);
    k3_t<<<dim3(3, Bb, 8), 128>>>();
    k4_cv<<<Bb, 256>>>(wqkv, bqkv);
    k5_gemm<0><<<dim3(6, 512), 256, K5_SMEM>>>(bqkv, nullptr);
    k5_gemm<1><<<dim3(6, 512), 256, K5_SMEM>>>(bout, out);
}

// round 6
// speedup vs baseline: 1.0166x; 1.0166x over previous
#include <cuda_runtime.h>
#include <cuda_bf16.h>
#include <cstdint>

#define Bb 64
#define Nn 1024
#define Cc 768
#define NHh 12
#define KDd 64
#define MROWS (Bb * Nn)

// ---------------- scratch ---------------------------------------------------
__device__ float g_q[Bb * NHh * Nn];
__device__ float g_w[Bb * NHh * Nn];
__device__ float g_sig[Bb * NHh];
__device__ float g_tp[Bb * 8 * NHh * Cc];
__device__ float g_cv[Bb * Cc];
__device__ __align__(16) __nv_bfloat16 g_xb[(size_t)MROWS * Cc];
__device__ __align__(16) __nv_bfloat16 g_vb[(size_t)MROWS * Cc];
__device__ __align__(16) __nv_bfloat16 g_wvb[Cc * Cc];
__device__ __align__(16) __nv_bfloat16 g_wob[Cc * Cc];

__device__ __forceinline__ uint32_t f2bf2(float lo, float hi) {
    uint32_t r;
    asm("cvt.rn.bf16x2.f32 %0, %1, %2;" : "=r"(r) : "f"(hi), "f"(lo));
    return r;
}
__device__ __forceinline__ uint32_t smem_u32(const void* p) {
    uint32_t a;
    asm("{ .reg .u64 t; cvta.to.shared.u64 t, %1; cvt.u32.u64 %0, t; }" : "=r"(a) : "l"(p));
    return a;
}
#define CP_COMMIT() asm volatile("cp.async.commit_group;" ::: "memory")
#define CP_WAIT1() asm volatile("cp.async.wait_group 1;" ::: "memory")

__device__ __forceinline__ void ldsm4(uint32_t& r0, uint32_t& r1, uint32_t& r2,
                                      uint32_t& r3, uint32_t a) {
    asm volatile("ldmatrix.sync.aligned.m8n8.x4.shared.b16 {%0,%1,%2,%3}, [%4];"
                 : "=r"(r0), "=r"(r1), "=r"(r2), "=r"(r3) : "r"(a));
}
__device__ __forceinline__ void mma_bf16(float c[4], const uint32_t a[4],
                                         const uint32_t b0, const uint32_t b1) {
    asm volatile(
        "mma.sync.aligned.m16n8k16.row.col.f32.bf16.bf16.f32 "
        "{%0,%1,%2,%3}, {%4,%5,%6,%7}, {%8,%9}, {%0,%1,%2,%3};"
        : "+f"(c[0]), "+f"(c[1]), "+f"(c[2]), "+f"(c[3])
        : "r"(a[0]), "r"(a[1]), "r"(a[2]), "r"(a[3]), "r"(b0), "r"(b1));
}

// ---------------- K0: weight conversion ------------------------------------
__global__ void __launch_bounds__(256) k0_wconv(const float* __restrict__ wqkv,
                                                const float* __restrict__ wout) {
    int o = blockIdx.x;
    int h = o >> 6, d = o & 63;
    const float2* s1 = (const float2*)(wqkv + (size_t)(h * 129 + 65 + d) * Cc);
    const float2* s2 = (const float2*)(wout + (size_t)o * Cc);
    uint32_t* d1 = (uint32_t*)g_wvb + o * (Cc / 2);
    uint32_t* d2 = (uint32_t*)g_wob + o * (Cc / 2);
    for (int i = threadIdx.x; i < Cc / 2; i += 256) {
        float2 a = s1[i]; d1[i] = f2bf2(a.x, a.y);
        float2 b = s2[i]; d2[i] = f2bf2(b.x, b.y);
    }
}

// ---------------- K1: q projection + x->bf16 --------------------------------
__global__ void __launch_bounds__(256) k1_qproj(const float* __restrict__ x,
                                                const float* __restrict__ wqkv,
                                                const float* __restrict__ bqkv) {
    __shared__ float sW[NHh][Cc];
    __shared__ float sB[NHh];
    int tid = threadIdx.x;
    for (int i = tid; i < NHh * Cc; i += 256) {
        int h = i / Cc, c = i % Cc;
        sW[h][c] = wqkv[(h * 129) * Cc + c];
    }
    if (tid < NHh) sB[tid] = bqkv[tid * 129];
    __syncthreads();

    int warp = tid >> 5, lane = tid & 31;
    int row0 = blockIdx.x * 128;
    for (int r = row0 + warp; r < row0 + 128; r += 8) {
        const float2* xr = (const float2*)(x + (size_t)r * Cc);
        uint32_t* xb = (uint32_t*)g_xb + (size_t)r * (Cc / 2);
        float acc[NHh];
#pragma unroll
        for (int h = 0; h < NHh; h++) acc[h] = 0.f;
#pragma unroll
        for (int i = 0; i < 12; i++) {
            int cp = lane + 32 * i;
            float2 xv = xr[cp];
            xb[cp] = f2bf2(xv.x, xv.y);
            int c = cp * 2;
#pragma unroll
            for (int h = 0; h < NHh; h++)
                acc[h] += xv.x * sW[h][c] + xv.y * sW[h][c + 1];
        }
#pragma unroll
        for (int h = 0; h < NHh; h++) {
#pragma unroll
            for (int off = 16; off; off >>= 1)
                acc[h] += __shfl_xor_sync(0xffffffffu, acc[h], off);
        }
        if (lane == 0) {
            int b = r >> 10, n = r & 1023;
#pragma unroll
            for (int h = 0; h < NHh; h++)
                g_q[((size_t)b * NHh + h) * Nn + n] = acc[h] + sB[h];
        }
    }
}

// ---------------- K2: softmax + *w_cv + sigma -------------------------------
__global__ void __launch_bounds__(256) k2_softmax(const float* __restrict__ wcv) {
    int bh = blockIdx.x;
    int tid = threadIdx.x;
    const float* q = g_q + (size_t)bh * Nn;
    __shared__ float red[256];

    float v0[4];
    float m = -1e30f;
#pragma unroll
    for (int i = 0; i < 4; i++) { v0[i] = q[tid + 256 * i]; m = fmaxf(m, v0[i]); }
    red[tid] = m; __syncthreads();
    for (int s = 128; s; s >>= 1) { if (tid < s) red[tid] = fmaxf(red[tid], red[tid + s]); __syncthreads(); }
    m = red[0]; __syncthreads();

    float e[4]; float sum = 0.f;
#pragma unroll
    for (int i = 0; i < 4; i++) { e[i] = expf(v0[i] - m); sum += e[i]; }
    red[tid] = sum; __syncthreads();
    for (int s = 128; s; s >>= 1) { if (tid < s) red[tid] += red[tid + s]; __syncthreads(); }
    float inv = 1.f / red[0]; __syncthreads();

    float wsum = 0.f;
#pragma unroll
    for (int i = 0; i < 4; i++) {
        int n = tid + 256 * i;
        float wv = e[i] * inv * wcv[n];
        g_w[(size_t)bh * Nn + n] = wv;
        wsum += wv;
    }
    red[tid] = wsum; __syncthreads();
    for (int s = 128; s; s >>= 1) { if (tid < s) red[tid] += red[tid + s]; __syncthreads(); }
    if (tid == 0) g_sig[bh] = red[0];
}

// ---------------- K3: t partials over 8 n-chunks ----------------------------
__global__ void __launch_bounds__(128) k3_t() {
    int b = blockIdx.y;
    int ch = blockIdx.z;
    int cp = blockIdx.x * 128 + threadIdx.x;
    __shared__ float sw[NHh * 128];
    for (int h = 0; h < NHh; h++)
        sw[h * 128 + threadIdx.x] = g_w[((size_t)b * NHh + h) * Nn + ch * 128 + threadIdx.x];
    __syncthreads();

    float acc0[NHh], acc1[NHh];
#pragma unroll
    for (int h = 0; h < NHh; h++) { acc0[h] = 0.f; acc1[h] = 0.f; }
    const uint32_t* xb = (const uint32_t*)g_xb + ((size_t)b * Nn + ch * 128) * (Cc / 2) + cp;
#pragma unroll 4
    for (int n = 0; n < 128; n++) {
        uint32_t u = xb[(size_t)n * (Cc / 2)];
        float lo = __uint_as_float(u << 16);
        float hi = __uint_as_float(u & 0xffff0000u);
#pragma unroll
        for (int h = 0; h < NHh; h++) {
            float wv = sw[h * 128 + n];
            acc0[h] += lo * wv;
            acc1[h] += hi * wv;
        }
    }
    float* tp = g_tp + ((size_t)(b * 8 + ch) * NHh) * Cc;
#pragma unroll
    for (int h = 0; h < NHh; h++) {
        tp[h * Cc + 2 * cp] = acc0[h];
        tp[h * Cc + 2 * cp + 1] = acc1[h];
    }
}

// ---------------- K4: cv ----------------------------------------------------
__global__ void __launch_bounds__(256) k4_cv(const float* __restrict__ wqkv,
                                             const float* __restrict__ bqkv) {
    int b = blockIdx.x;
    __shared__ float st[NHh * Cc];
    for (int i = threadIdx.x; i < NHh * Cc; i += 256) {
        float s = 0.f;
#pragma unroll
        for (int ch = 0; ch < 8; ch++)
            s += g_tp[((size_t)(b * 8 + ch) * NHh) * Cc + i];
        st[i] = s;
    }
    __syncthreads();

    int tid = threadIdx.x;
    int i0 = tid, i1 = tid + 256, i2 = tid + 512;
    int h0 = i0 >> 6, d0 = i0 & 63;
    int h1 = i1 >> 6, d1 = i1 & 63;
    int h2 = i2 >> 6, d2 = i2 & 63;
    const float4* w0 = (const float4*)(wqkv + (size_t)(h0 * 129 + 1 + d0) * Cc);
    const float4* w1 = (const float4*)(wqkv + (size_t)(h1 * 129 + 1 + d1) * Cc);
    const float4* w2 = (const float4*)(wqkv + (size_t)(h2 * 129 + 1 + d2) * Cc);
    const float4* t0 = (const float4*)(st + h0 * Cc);
    const float4* t1 = (const float4*)(st + h1 * Cc);
    const float4* t2 = (const float4*)(st + h2 * Cc);
    float a0 = 0.f, a1 = 0.f, a2 = 0.f;
#pragma unroll 4
    for (int i = 0; i < Cc / 4; i++) {
        float4 wa = w0[i], ta = t0[i];
        a0 += wa.x * ta.x + wa.y * ta.y + wa.z * ta.z + wa.w * ta.w;
        float4 wb = w1[i], tb = t1[i];
        a1 += wb.x * tb.x + wb.y * tb.y + wb.z * tb.z + wb.w * tb.w;
        float4 wc = w2[i], tc = t2[i];
        a2 += wc.x * tc.x + wc.y * tc.y + wc.z * tc.z + wc.w * tc.w;
    }
    g_cv[b * Cc + i0] = a0 + bqkv[h0 * 129 + 1 + d0] * g_sig[b * NHh + h0];
    g_cv[b * Cc + i1] = a1 + bqkv[h1 * 129 + 1 + d1] * g_sig[b * NHh + h1];
    g_cv[b * Cc + i2] = a2 + bqkv[h2 * 129 + 1 + d2] * g_sig[b * NHh + h2];
}

// ---------------- K5: bf16 HMMA GEMM, 128x128x64, 4 warps, 64x64 warp tile --
// MODE 0: A=g_xb, B=g_wvb, epilogue relu(v+bv)*cv -> g_vb (bf16)
// MODE 1: A=g_vb, B=g_wob, epilogue +b_out        -> out  (fp32)
#define K5_STAGES 3
#define K5_STAGE_BYTES 32768
#define K5_SMEM (K5_STAGES * K5_STAGE_BYTES)

template <int MODE>
__global__ void __launch_bounds__(128, 2) k5_gemm(const float* __restrict__ bias,
                                                  float* __restrict__ outg) {
    extern __shared__ char smem[];
    const uint32_t tb = smem_u32(smem);

    const int tid = threadIdx.x;
    const int warp = tid >> 5, lane = tid & 31;
    const int wm = warp >> 1, wn = warp & 1;     // 2x2 warp grid, 64x64 warp tile
    const int gid = lane >> 2, tg = lane & 3;
    const int seg = lane >> 3, l7 = lane & 7;
    const int arow0 = blockIdx.y * 128;
    const int brow0 = blockIdx.x * 128;

    const __nv_bfloat16* Ab = (MODE == 0) ? g_xb : g_vb;
    const __nv_bfloat16* Bm = (MODE == 0) ? g_wvb : g_wob;

    // ---- loads: 128 threads; thread covers rows (tid>>3)+16*i, 16B chunk (tid&7)
    // smem slot stride 2048 (16 rows * 128B), global slot stride 24576 (16*768*2)
    const char* gA = (const char*)Ab + ((size_t)(arow0 + (tid >> 3)) * 96 + (tid & 7)) * 16;
    const char* gB = (const char*)Bm + ((size_t)(brow0 + (tid >> 3)) * 96 + (tid & 7)) * 16;
    const uint32_t swo0 = (uint32_t)((tid >> 3) * 128 + (((tid & 7) ^ ((tid >> 3) & 7)) * 16));

    // ---- ldmatrix addressing ----
    const uint32_t aRowOff = (uint32_t)((wm * 64 + (seg & 1) * 8 + l7) * 128);
    const uint32_t bRowOff = (uint32_t)((wn * 64 + (seg >> 1) * 8 + l7) * 128);
    const uint32_t kselA = (uint32_t)(seg >> 1);
    const uint32_t kselB = (uint32_t)(seg & 1);

    float acc[4][8][4];
#pragma unroll
    for (int mi = 0; mi < 4; mi++)
#pragma unroll
        for (int ni = 0; ni < 8; ni++)
#pragma unroll
            for (int rg = 0; rg < 4; rg++) acc[mi][ni][rg] = 0.f;

#define K5_LOAD(kc, s)                                                          \
    do {                                                                        \
        uint32_t _aT = tb + (s) * K5_STAGE_BYTES + swo0;                        \
        uint32_t _bT = _aT + 16384;                                             \
        const char* _ga = gA + (kc) * 128;                                      \
        const char* _gb = gB + (kc) * 128;                                      \
        asm volatile(                                                           \
            "cp.async.cg.shared.global [%0], [%2], 16;\n\t"                     \
            "cp.async.cg.shared.global [%0+2048], [%2+24576], 16;\n\t"          \
            "cp.async.cg.shared.global [%0+4096], [%2+49152], 16;\n\t"          \
            "cp.async.cg.shared.global [%0+6144], [%2+73728], 16;\n\t"          \
            "cp.async.cg.shared.global [%0+8192], [%2+98304], 16;\n\t"          \
            "cp.async.cg.shared.global [%0+10240], [%2+122880], 16;\n\t"        \
            "cp.async.cg.shared.global [%0+12288], [%2+147456], 16;\n\t"        \
            "cp.async.cg.shared.global [%0+14336], [%2+172032], 16;\n\t"        \
            "cp.async.cg.shared.global [%1], [%3], 16;\n\t"                     \
            "cp.async.cg.shared.global [%1+2048], [%3+24576], 16;\n\t"          \
            "cp.async.cg.shared.global [%1+4096], [%3+49152], 16;\n\t"          \
            "cp.async.cg.shared.global [%1+6144], [%3+73728], 16;\n\t"          \
            "cp.async.cg.shared.global [%1+8192], [%3+98304], 16;\n\t"          \
            "cp.async.cg.shared.global [%1+10240], [%3+122880], 16;\n\t"        \
            "cp.async.cg.shared.global [%1+12288], [%3+147456], 16;\n\t"        \
            "cp.async.cg.shared.global [%1+14336], [%3+172032], 16;\n\t"        \
            :: "r"(_aT), "r"(_bT), "l"(_ga), "l"(_gb));                         \
    } while (0)

    K5_LOAD(0, 0); CP_COMMIT();
    K5_LOAD(1, 1); CP_COMMIT();

#pragma unroll 1
    for (int kc = 0; kc < 12; kc++) {
        CP_WAIT1();               // group for kc complete; kc+1 may be in flight
        __syncthreads();          // all warps done reading stage (kc-1)%3
        if (kc + 2 < 12) K5_LOAD(kc + 2, (kc + 2) % K5_STAGES);
        CP_COMMIT();

        const uint32_t stBase = tb + (kc % K5_STAGES) * K5_STAGE_BYTES;
        const uint32_t aT = stBase + aRowOff;
        const uint32_t bT = stBase + 16384 + bRowOff;

#pragma unroll
        for (int ks = 0; ks < 4; ks++) {
            const uint32_t xa = (((uint32_t)(ks * 2) + kselA) ^ (uint32_t)l7) * 16u;
            const uint32_t xb = (((uint32_t)(ks * 2) + kselB) ^ (uint32_t)l7) * 16u;
            uint32_t af[4][4];
            uint32_t bf[4][4];
            const uint32_t a0 = aT + xa;
            ldsm4(af[0][0], af[0][1], af[0][2], af[0][3], a0);
            ldsm4(af[1][0], af[1][1], af[1][2], af[1][3], a0 + 2048);
            ldsm4(af[2][0], af[2][1], af[2][2], af[2][3], a0 + 4096);
            ldsm4(af[3][0], af[3][1], af[3][2], af[3][3], a0 + 6144);
            const uint32_t b0 = bT + xb;
            ldsm4(bf[0][0], bf[0][1], bf[0][2], bf[0][3], b0);
            ldsm4(bf[1][0], bf[1][1], bf[1][2], bf[1][3], b0 + 2048);
            ldsm4(bf[2][0], bf[2][1], bf[2][2], bf[2][3], b0 + 4096);
            ldsm4(bf[3][0], bf[3][1], bf[3][2], bf[3][3], b0 + 6144);
#pragma unroll
            for (int mi = 0; mi < 4; mi++) {
#pragma unroll
                for (int n2 = 0; n2 < 4; n2++) {
                    mma_bf16(acc[mi][2 * n2], af[mi], bf[n2][0], bf[n2][1]);
                    mma_bf16(acc[mi][2 * n2 + 1], af[mi], bf[n2][2], bf[n2][3]);
                }
            }
        }
    }

    // epilogue
#pragma unroll
    for (int mi = 0; mi < 4; mi++) {
        int row = arow0 + wm * 64 + mi * 16 + gid;
#pragma unroll
        for (int ni = 0; ni < 8; ni++) {
            int col = brow0 + wn * 64 + ni * 8 + tg * 2;
            if (MODE == 0) {
                int hb = (col >> 6) * 129 + 65 + (col & 63);
                float bv0 = bias[hb], bv1 = bias[hb + 1];
                int b = row >> 10;
                float cv0 = g_cv[b * Cc + col], cv1 = g_cv[b * Cc + col + 1];
                float v00 = fmaxf(acc[mi][ni][0] + bv0, 0.f) * cv0;
                float v01 = fmaxf(acc[mi][ni][1] + bv1, 0.f) * cv1;
                float v10 = fmaxf(acc[mi][ni][2] + bv0, 0.f) * cv0;
                float v11 = fmaxf(acc[mi][ni][3] + bv1, 0.f) * cv1;
                uint32_t* dst = (uint32_t*)g_vb;
                dst[(size_t)row * (Cc / 2) + col / 2] = f2bf2(v00, v01);
                dst[(size_t)(row + 8) * (Cc / 2) + col / 2] = f2bf2(v10, v11);
            } else {
                float b0 = bias[col], b1 = bias[col + 1];
                *(float2*)(outg + (size_t)row * Cc + col) =
                    make_float2(acc[mi][ni][0] + b0, acc[mi][ni][1] + b1);
                *(float2*)(outg + (size_t)(row + 8) * Cc + col) =
                    make_float2(acc[mi][ni][2] + b0, acc[mi][ni][3] + b1);
            }
        }
    }
}

// ---------------- launch ----------------------------------------------------
extern "C" void kernel_launch(void* const* d_in, const int* in_sizes, int n_in,
                              void* d_out, int out_size) {
    const float* x = (const float*)d_in[0];
    const float* wqkv = (const float*)d_in[1];
    const float* bqkv = (const float*)d_in[2];
    const float* wcv = (const float*)d_in[3];
    const float* wout = (const float*)d_in[4];
    const float* bout = (const float*)d_in[5];
    float* out = (float*)d_out;

    cudaFuncSetAttribute(k5_gemm<0>, cudaFuncAttributeMaxDynamicSharedMemorySize, K5_SMEM);
    cudaFuncSetAttribute(k5_gemm<1>, cudaFuncAttributeMaxDynamicSharedMemorySize, K5_SMEM);

    k0_wconv<<<Cc, 256>>>(wqkv, wout);
    k1_qproj<<<512, 256>>>(x, wqkv, bqkv);
    k2_softmax<<<Bb * NHh, 256>>>(wcv);
    k3_t<<<dim3(3, Bb, 8), 128>>>();
    k4_cv<<<Bb, 256>>>(wqkv, bqkv);
    k5_gemm<0><<<dim3(6, 512), 128, K5_SMEM>>>(bqkv, nullptr);
    k5_gemm<1><<<dim3(6, 512), 128, K5_SMEM>>>(bout, out);
}